// round 1
// baseline (speedup 1.0000x reference)
#include <cuda_runtime.h>
#include <math.h>

// Problem: loss over pairwise sq-distances between Z[N,D] and E[M,D].
// lse_j = logsumexp_i( alpha*(z2_i + e2_j - 2 dot_ij) )
//       = alpha*e2_j + logsumexp_i( alpha*z2_i - 2*alpha*dot_ij )
// loss = -mean_j(lse_j) + 0.5*D*(2*log_sigma - 1) + log(N)

#define DDIM 512
#define BM 128   // rows (i / N dim) per chunk
#define BN 64    // cols (j / M dim) per CTA
#define BK 16
#define TM 8
#define TN 4

__device__ float g_z2[8192];
__device__ float g_e2[8192];
__device__ double g_acc;

// One warp per row: squared L2 norms of all Z and E rows. Block 0 / thread 0
// also zeroes the global accumulator (stream order guarantees it lands before
// the fused kernel runs).
__global__ void norms_kernel(const float* __restrict__ Z,
                             const float* __restrict__ E,
                             int N, int M) {
    if (blockIdx.x == 0 && threadIdx.x == 0) g_acc = 0.0;
    int gw = (blockIdx.x * blockDim.x + threadIdx.x) >> 5;
    int lane = threadIdx.x & 31;
    if (gw >= N + M) return;
    const float* row = (gw < N) ? (Z + (size_t)gw * DDIM)
                                : (E + (size_t)(gw - N) * DDIM);
    float s = 0.f;
    #pragma unroll 4
    for (int c = lane; c < DDIM; c += 32) {
        float v = row[c];
        s = fmaf(v, v, s);
    }
    #pragma unroll
    for (int o = 16; o; o >>= 1) s += __shfl_xor_sync(0xffffffffu, s, o);
    if (lane == 0) {
        if (gw < N) g_z2[gw] = s;
        else        g_e2[gw - N] = s;
    }
}

// Each CTA owns a BN-column slab of E, streams all N rows of Z in BM chunks,
// computes the dot-product tile with a register-tiled fp32 GEMM, and maintains
// an exact online logsumexp per column. Per-column LSE is finished in-CTA and
// the slab sum is atomically merged (double) into g_acc.
__global__ void __launch_bounds__(256, 1) fused_gemm_lse(
    const float* __restrict__ Z, const float* __restrict__ E,
    const float* __restrict__ log_sigma, int N, int M)
{
    __shared__ float smem[BK * BM + BK * BN];  // 3072 floats = 12 KB
    float (*As)[BM] = reinterpret_cast<float(*)[BM]>(smem);
    float (*Bs)[BN] = reinterpret_cast<float(*)[BN]>(smem + BK * BM);

    const int tid = threadIdx.x;
    const int tx = tid & 15;   // column group: cols tx*4 .. tx*4+3
    const int ty = tid >> 4;   // row group:    rows ty*8 .. ty*8+7
    const int j0 = blockIdx.x * BN;

    const float ls    = __ldg(log_sigma);
    const float alpha = -0.5f * __expf(-2.f * ls);   // -1/(2*exp(ls)^2)
    const float m2a   = -2.f * alpha;

    float mx[TN], sv[TN];
    #pragma unroll
    for (int b = 0; b < TN; b++) { mx[b] = -INFINITY; sv[b] = 0.f; }

    const int a_r = tid >> 2;        // 0..63
    const int a_c = (tid & 3) << 2;  // 0,4,8,12

    for (int i0 = 0; i0 < N; i0 += BM) {
        float acc[TM][TN];
        #pragma unroll
        for (int a = 0; a < TM; a++)
            #pragma unroll
            for (int b = 0; b < TN; b++) acc[a][b] = 0.f;

        for (int k0 = 0; k0 < DDIM; k0 += BK) {
            // load Z tile (BM x BK) transposed into As[BK][BM]
            #pragma unroll
            for (int p = 0; p < 2; p++) {
                float4 v = *reinterpret_cast<const float4*>(
                    Z + (size_t)(i0 + a_r + p * 64) * DDIM + k0 + a_c);
                As[a_c + 0][a_r + p * 64] = v.x;
                As[a_c + 1][a_r + p * 64] = v.y;
                As[a_c + 2][a_r + p * 64] = v.z;
                As[a_c + 3][a_r + p * 64] = v.w;
            }
            // load E tile (BN x BK) transposed into Bs[BK][BN]
            {
                float4 v = *reinterpret_cast<const float4*>(
                    E + (size_t)(j0 + a_r) * DDIM + k0 + a_c);
                Bs[a_c + 0][a_r] = v.x;
                Bs[a_c + 1][a_r] = v.y;
                Bs[a_c + 2][a_r] = v.z;
                Bs[a_c + 3][a_r] = v.w;
            }
            __syncthreads();

            #pragma unroll
            for (int k = 0; k < BK; k++) {
                float4 a0 = *reinterpret_cast<const float4*>(&As[k][ty * TM]);
                float4 a1 = *reinterpret_cast<const float4*>(&As[k][ty * TM + 4]);
                float4 b0 = *reinterpret_cast<const float4*>(&Bs[k][tx * TN]);
                float ra[TM] = {a0.x, a0.y, a0.z, a0.w, a1.x, a1.y, a1.z, a1.w};
                float rb[TN] = {b0.x, b0.y, b0.z, b0.w};
                #pragma unroll
                for (int a = 0; a < TM; a++)
                    #pragma unroll
                    for (int b = 0; b < TN; b++)
                        acc[a][b] = fmaf(ra[a], rb[b], acc[a][b]);
            }
            __syncthreads();
        }

        // online-logsumexp epilogue for this row chunk
        float az2[TM];
        #pragma unroll
        for (int a = 0; a < TM; a++)
            az2[a] = alpha * __ldg(&g_z2[i0 + ty * TM + a]);

        #pragma unroll
        for (int b = 0; b < TN; b++) {
            float s[TM], cmax = -INFINITY;
            #pragma unroll
            for (int a = 0; a < TM; a++) {
                s[a] = fmaf(m2a, acc[a][b], az2[a]);
                cmax = fmaxf(cmax, s[a]);
            }
            if (cmax > mx[b]) {                 // exp(-inf)=0 handles 1st chunk
                sv[b] *= __expf(mx[b] - cmax);
                mx[b] = cmax;
            }
            #pragma unroll
            for (int a = 0; a < TM; a++) sv[b] += __expf(s[a] - mx[b]);
        }
    }

    // merge the 16 (ty) partial softmax states per column via smem
    __syncthreads();
    float (*RM)[BN] = reinterpret_cast<float(*)[BN]>(smem);
    float (*RS)[BN] = reinterpret_cast<float(*)[BN]>(smem + 16 * BN);
    #pragma unroll
    for (int b = 0; b < TN; b++) {
        RM[ty][tx * TN + b] = mx[b];
        RS[ty][tx * TN + b] = sv[b];
    }
    __syncthreads();

    float lse = 0.f;
    if (tid < BN) {
        int j = tid;
        float gm = -INFINITY;
        #pragma unroll
        for (int t = 0; t < 16; t++) gm = fmaxf(gm, RM[t][j]);
        float gs = 0.f;
        #pragma unroll
        for (int t = 0; t < 16; t++) gs += RS[t][j] * __expf(RM[t][j] - gm);
        lse = alpha * __ldg(&g_e2[j0 + j]) + gm + logf(gs);
    }

    // block-reduce sum of the BN lse values, one double atomic per CTA
    #pragma unroll
    for (int o = 16; o; o >>= 1) lse += __shfl_xor_sync(0xffffffffu, lse, o);
    __shared__ float wsum[8];
    if ((tid & 31) == 0) wsum[tid >> 5] = lse;
    __syncthreads();
    if (tid == 0) {
        float tot = 0.f;
        #pragma unroll
        for (int w = 0; w < 8; w++) tot += wsum[w];
        atomicAdd(&g_acc, (double)tot);
    }
}

__global__ void finalize_kernel(const float* __restrict__ log_sigma,
                                float* __restrict__ out, int N, int M) {
    float ls = *log_sigma;
    float loss = -(float)(g_acc / (double)M)
               + 0.5f * (float)DDIM * (2.f * ls - 1.f)
               + logf((float)N);
    out[0] = loss;
}

extern "C" void kernel_launch(void* const* d_in, const int* in_sizes, int n_in,
                              void* d_out, int out_size) {
    const float* Z  = (const float*)d_in[0];
    const float* E  = (const float*)d_in[1];
    const float* ls = (const float*)d_in[2];
    int N = in_sizes[0] / DDIM;
    int M = in_sizes[1] / DDIM;
    float* out = (float*)d_out;

    int rows = N + M;
    int nb = (rows * 32 + 255) / 256;
    norms_kernel<<<nb, 256>>>(Z, E, N, M);
    fused_gemm_lse<<<M / BN, 256>>>(Z, E, ls, N, M);
    finalize_kernel<<<1, 1>>>(ls, out, N, M);
}

// round 3
// speedup vs baseline: 4.8557x; 4.8557x over previous
#include <cuda_runtime.h>
#include <math.h>
#include <stdint.h>

// loss = -mean_j [ alpha*e2_j + logsumexp_i( alpha*z2_i - 2*alpha*<z_i,e_j> ) ]
//        + 0.5*D*(2*ls - 1) + log(N)
// GEMM via mma.sync.m16n8k8.tf32 (compute_103-safe; no tcgen05).
// Inputs pre-rounded to tf32 (cvt.rna) to avoid truncation bias.
// Online LSE in log2 space on register accumulators.

#define NROWS 8192
#define MROWS 8192
#define DDIM  512

#define JTILE 128                  // E rows per CTA (m)
#define ITILE 256                  // Z rows per chunk (n)
#define KT    32                   // k per pipeline stage
#define NSPLIT 2
#define IRANGE (NROWS / NSPLIT)    // 4096
#define NCHUNK (IRANGE / ITILE)    // 16
#define KSTAGES (DDIM / KT)        // 16
#define TOTSTAGES (NCHUNK * KSTAGES)  // 256

#define SROW 36                    // padded row stride in floats (bank-optimal)
#define A_FLOATS (JTILE * SROW)    // 4608
#define B_FLOATS (ITILE * SROW)    // 9216
#define STG_FLOATS (A_FLOATS + B_FLOATS)
#define NBUF 4

#define LOG2E 1.4426950408889634f
#define LN2   0.6931471805599453f

__device__ float g_ztf[NROWS * DDIM];   // tf32-rounded copies
__device__ float g_etf[MROWS * DDIM];
__device__ float g_z2[NROWS];
__device__ float g_e2[MROWS];
__device__ float g_pm[NSPLIT * MROWS];  // per-(split,j) partial max (log2 units)
__device__ float g_ps[NSPLIT * MROWS];  // per-(split,j) partial sum

__device__ __forceinline__ float round_tf32(float x) {
    float r; asm("cvt.rna.tf32.f32 %0, %1;" : "=f"(r) : "f"(x)); return r;
}
__device__ __forceinline__ float fast_exp2(float x) {
    float r; asm("ex2.approx.ftz.f32 %0, %1;" : "=f"(r) : "f"(x)); return r;
}
__device__ __forceinline__ void mma_tf32(float* d, const float* a, const float* b) {
    asm volatile(
        "mma.sync.aligned.m16n8k8.row.col.f32.tf32.tf32.f32 "
        "{%0,%1,%2,%3}, {%4,%5,%6,%7}, {%8,%9}, {%0,%1,%2,%3};"
        : "+f"(d[0]), "+f"(d[1]), "+f"(d[2]), "+f"(d[3])
        : "r"(__float_as_uint(a[0])), "r"(__float_as_uint(a[1])),
          "r"(__float_as_uint(a[2])), "r"(__float_as_uint(a[3])),
          "r"(__float_as_uint(b[0])), "r"(__float_as_uint(b[1])));
}
__device__ __forceinline__ void cp16(float* smem_dst, const float* gmem_src) {
    uint32_t d = (uint32_t)__cvta_generic_to_shared(smem_dst);
    asm volatile("cp.async.cg.shared.global [%0], [%1], 16;"
                 :: "r"(d), "l"(gmem_src) : "memory");
}

// ---- prep: exact row norms + tf32-rounded copies (one warp per row) ----
__global__ void prep_kernel(const float* __restrict__ Z, const float* __restrict__ E) {
    int gw = (blockIdx.x * blockDim.x + threadIdx.x) >> 5;
    int lane = threadIdx.x & 31;
    if (gw >= NROWS + MROWS) return;
    const float4* src; float4* dst;
    if (gw < NROWS) { src = (const float4*)(Z + (size_t)gw * DDIM);
                      dst = (float4*)(g_ztf + (size_t)gw * DDIM); }
    else            { src = (const float4*)(E + (size_t)(gw - NROWS) * DDIM);
                      dst = (float4*)(g_etf + (size_t)(gw - NROWS) * DDIM); }
    float s = 0.f;
    #pragma unroll
    for (int u = 0; u < DDIM / 4 / 32; u++) {
        float4 v = src[u * 32 + lane];
        s = fmaf(v.x, v.x, s); s = fmaf(v.y, v.y, s);
        s = fmaf(v.z, v.z, s); s = fmaf(v.w, v.w, s);
        float4 rv;
        rv.x = round_tf32(v.x); rv.y = round_tf32(v.y);
        rv.z = round_tf32(v.z); rv.w = round_tf32(v.w);
        dst[u * 32 + lane] = rv;
    }
    #pragma unroll
    for (int o = 16; o; o >>= 1) s += __shfl_xor_sync(0xffffffffu, s, o);
    if (lane == 0) { if (gw < NROWS) g_z2[gw] = s; else g_e2[gw - NROWS] = s; }
}

// ---- fused tf32 mma.sync GEMM + online logsumexp ----
__global__ void __launch_bounds__(256, 1) fused_mma_lse(const float* __restrict__ log_sigma) {
    extern __shared__ float smem[];
    float* stg = smem;                           // NBUF * STG_FLOATS
    float* az2 = smem + NBUF * STG_FLOATS;       // 2 * ITILE
    float* smm = az2 + 2 * ITILE;                // 4 * JTILE
    float* sms = smm + 4 * JTILE;                // 4 * JTILE

    const int tid = threadIdx.x, lane = tid & 31, wid = tid >> 5;
    const int wm = wid & 1, wn = wid >> 1;       // 2 x 4 warp grid
    const int g = lane >> 2, cql = lane & 3;
    const int jslab = blockIdx.x >> 1, split = blockIdx.x & 1;
    const int j0 = jslab * JTILE, ibase = split * IRANGE;

    const float ls = __ldg(log_sigma);
    const float alpha = -0.5f * __expf(-2.f * ls);
    const float coefD = LOG2E * (-2.f * alpha);
    const float coefA = LOG2E * alpha;

    float acc[4][8][4];
    #pragma unroll
    for (int mt = 0; mt < 4; mt++)
        #pragma unroll
        for (int nt = 0; nt < 8; nt++)
            #pragma unroll
            for (int q = 0; q < 4; q++) acc[mt][nt][q] = 0.f;
    float mx[8], sv[8];
    #pragma unroll
    for (int r = 0; r < 8; r++) { mx[r] = -INFINITY; sv[r] = 0.f; }

    auto issue_stage = [&](int s) {
        float* base = stg + (s & (NBUF - 1)) * STG_FLOATS;
        int koff = (s & (KSTAGES - 1)) * KT;
        int i0 = ibase + (s >> 4) * ITILE;
        #pragma unroll
        for (int q = 0; q < 4; q++) {           // A = E slab: 128 rows x 32
            int uid = q * 256 + tid, row = uid >> 3, c16 = uid & 7;
            cp16(base + row * SROW + c16 * 4,
                 g_etf + (size_t)(j0 + row) * DDIM + koff + c16 * 4);
        }
        #pragma unroll
        for (int q = 0; q < 8; q++) {           // B = Z chunk: 256 rows x 32
            int uid = q * 256 + tid, row = uid >> 3, c16 = uid & 7;
            cp16(base + A_FLOATS + row * SROW + c16 * 4,
                 g_ztf + (size_t)(i0 + row) * DDIM + koff + c16 * 4);
        }
        asm volatile("cp.async.commit_group;" ::: "memory");
    };

    issue_stage(0);
    issue_stage(1);

    #pragma unroll 1
    for (int s = 0; s < TOTSTAGES; s++) {
        asm volatile("cp.async.wait_group 1;" ::: "memory");
        __syncthreads();
        const int t = s >> 4, ks = s & (KSTAGES - 1);
        if (ks == 0)  // stage alpha*z2 for this chunk (log2 units)
            az2[(t & 1) * ITILE + tid] = coefA * g_z2[ibase + t * ITILE + tid];
        if (s + 2 < TOTSTAGES) issue_stage(s + 2);

        const float* As = stg + (s & (NBUF - 1)) * STG_FLOATS;
        const float* Bs = As + A_FLOATS;
        #pragma unroll
        for (int kk = 0; kk < 4; kk++) {
            const int ko = kk * 8;
            float a[4][4], b[8][2];
            #pragma unroll
            for (int mt = 0; mt < 4; mt++) {
                const float* ap = As + (wm * 64 + mt * 16 + g) * SROW + ko + cql;
                a[mt][0] = ap[0]; a[mt][1] = ap[4];
                a[mt][2] = ap[8 * SROW]; a[mt][3] = ap[8 * SROW + 4];
            }
            #pragma unroll
            for (int nt = 0; nt < 8; nt++) {
                const float* bp = Bs + (wn * 64 + nt * 8 + g) * SROW + ko + cql;
                b[nt][0] = bp[0]; b[nt][1] = bp[4];
            }
            #pragma unroll
            for (int mt = 0; mt < 4; mt++)
                #pragma unroll
                for (int nt = 0; nt < 8; nt++)
                    mma_tf32(acc[mt][nt], a[mt], b[nt]);
        }

        if (ks == KSTAGES - 1) {
            // ---- epilogue for chunk t: deferred-rescale online LSE ----
            const float* a2 = az2 + (t & 1) * ITILE;
            float rmx[8];
            #pragma unroll
            for (int r = 0; r < 8; r++) rmx[r] = -INFINITY;
            #pragma unroll
            for (int mt = 0; mt < 4; mt++)
                #pragma unroll
                for (int nt = 0; nt < 8; nt++) {
                    int ib = wn * 64 + nt * 8 + 2 * cql;
                    float s0 = fmaf(coefD, acc[mt][nt][0], a2[ib]);
                    float s1 = fmaf(coefD, acc[mt][nt][1], a2[ib + 1]);
                    float s2 = fmaf(coefD, acc[mt][nt][2], a2[ib]);
                    float s3 = fmaf(coefD, acc[mt][nt][3], a2[ib + 1]);
                    acc[mt][nt][0] = s0; acc[mt][nt][1] = s1;
                    acc[mt][nt][2] = s2; acc[mt][nt][3] = s3;
                    rmx[mt * 2]     = fmaxf(rmx[mt * 2],     fmaxf(s0, s1));
                    rmx[mt * 2 + 1] = fmaxf(rmx[mt * 2 + 1], fmaxf(s2, s3));
                }
            #pragma unroll
            for (int r = 0; r < 8; r++) {
                float nm = fmaxf(mx[r], rmx[r]);
                sv[r] *= fast_exp2(mx[r] - nm);   // first chunk: 0 * ex2(-inf) = 0
                mx[r] = nm;
            }
            #pragma unroll
            for (int mt = 0; mt < 4; mt++) {
                float p0 = 0.f, p1 = 0.f;
                #pragma unroll
                for (int nt = 0; nt < 8; nt++) {
                    p0 += fast_exp2(acc[mt][nt][0] - mx[mt * 2])
                        + fast_exp2(acc[mt][nt][1] - mx[mt * 2]);
                    p1 += fast_exp2(acc[mt][nt][2] - mx[mt * 2 + 1])
                        + fast_exp2(acc[mt][nt][3] - mx[mt * 2 + 1]);
                    acc[mt][nt][0] = 0.f; acc[mt][nt][1] = 0.f;
                    acc[mt][nt][2] = 0.f; acc[mt][nt][3] = 0.f;
                }
                sv[mt * 2] += p0; sv[mt * 2 + 1] += p1;
            }
        }
    }

    // ---- merge the 4 lanes (cql) sharing each row ----
    #pragma unroll
    for (int r = 0; r < 8; r++) {
        #pragma unroll
        for (int off = 1; off < 4; off <<= 1) {
            float om = __shfl_xor_sync(0xffffffffu, mx[r], off);
            float os = __shfl_xor_sync(0xffffffffu, sv[r], off);
            float nm = fmaxf(mx[r], om);
            sv[r] = sv[r] * fast_exp2(mx[r] - nm) + os * fast_exp2(om - nm);
            mx[r] = nm;
        }
    }
    __syncthreads();   // stage buffers dead; reuse smm/sms region safely
    if (cql == 0) {
        #pragma unroll
        for (int r = 0; r < 8; r++) {
            int row = wm * 64 + (r >> 1) * 16 + (r & 1) * 8 + g;
            smm[wn * JTILE + row] = mx[r];
            sms[wn * JTILE + row] = sv[r];
        }
    }
    __syncthreads();
    if (tid < JTILE) {
        float gm = -INFINITY;
        #pragma unroll
        for (int w = 0; w < 4; w++) gm = fmaxf(gm, smm[w * JTILE + tid]);
        float gs = 0.f;
        #pragma unroll
        for (int w = 0; w < 4; w++)
            gs += sms[w * JTILE + tid] * fast_exp2(smm[w * JTILE + tid] - gm);
        g_pm[split * MROWS + j0 + tid] = gm;
        g_ps[split * MROWS + j0 + tid] = gs;
    }
}

// ---- finalize: merge splits, add e2 term, mean, constants ----
__global__ void finalize_kernel(const float* __restrict__ log_sigma,
                                float* __restrict__ out) {
    __shared__ double red[256];
    int tid = threadIdx.x;
    float ls = __ldg(log_sigma);
    float alpha = -0.5f * __expf(-2.f * ls);
    double acc = 0.0;
    for (int j = tid; j < MROWS; j += 256) {
        float m0 = g_pm[j],         s0 = g_ps[j];
        float m1 = g_pm[MROWS + j], s1 = g_ps[MROWS + j];
        float gm = fmaxf(m0, m1);
        float s = s0 * exp2f(m0 - gm) + s1 * exp2f(m1 - gm);
        float lse = alpha * g_e2[j] + LN2 * (gm + log2f(s));
        acc += (double)lse;
    }
    red[tid] = acc;
    __syncthreads();
    for (int o = 128; o; o >>= 1) { if (tid < o) red[tid] += red[tid + o]; __syncthreads(); }
    if (tid == 0)
        out[0] = (float)(-red[0] / (double)MROWS)
               + 0.5f * (float)DDIM * (2.f * ls - 1.f) + logf((float)NROWS);
}

extern "C" void kernel_launch(void* const* d_in, const int* in_sizes, int n_in,
                              void* d_out, int out_size) {
    const float* Z  = (const float*)d_in[0];
    const float* E  = (const float*)d_in[1];
    const float* ls = (const float*)d_in[2];
    float* out = (float*)d_out;

    static int smem_set = 0;
    int smem_bytes = (NBUF * STG_FLOATS + 2 * ITILE + 8 * JTILE) * 4;
    if (!smem_set) {
        cudaFuncSetAttribute(fused_mma_lse,
                             cudaFuncAttributeMaxDynamicSharedMemorySize, smem_bytes);
        smem_set = 1;
    }

    prep_kernel<<<(NROWS + MROWS) / 8, 256>>>(Z, E);
    fused_mma_lse<<<(MROWS / JTILE) * NSPLIT, 256, smem_bytes>>>(ls);
    finalize_kernel<<<1, 256>>>(ls, out);
}

// round 4
// speedup vs baseline: 10.7604x; 2.2160x over previous
#include <cuda_runtime.h>
#include <cuda_fp16.h>
#include <math.h>
#include <stdint.h>

// loss = -mean_j [ alpha*e2_j + logsumexp_i( alpha*z2_i - 2*alpha*<z_i,e_j> ) ]
//        + 0.5*D*(2*ls - 1) + log(N)
// GEMM via mma.sync.m16n8k16.f16 (fp32 accum), ldmatrix fragment loads,
// XOR-swizzled smem, cp.async pipeline. Online LSE in log2 space.

#define NROWS 8192
#define MROWS 8192
#define DDIM  512

#define JTILE 128                   // E rows per CTA (m)
#define ITILE 256                   // Z rows per chunk (n)
#define KT    64                    // k elements per stage (128B rows in fp16)
#define NSPLIT 2
#define IRANGE (NROWS / NSPLIT)     // 4096
#define NCHUNK (IRANGE / ITILE)     // 16
#define KSTAGES (DDIM / KT)         // 8
#define TOTSTAGES (NCHUNK * KSTAGES)  // 128

#define A_BYTES (JTILE * 128)       // 16384
#define B_BYTES (ITILE * 128)       // 32768
#define STAGE_BYTES (A_BYTES + B_BYTES)
#define NBUF 4

#define LOG2E 1.4426950408889634f
#define LN2   0.6931471805599453f

__device__ __half g_zh[NROWS * DDIM];   // fp16 copies (rne)
__device__ __half g_eh[MROWS * DDIM];
__device__ float g_z2[NROWS];
__device__ float g_e2[MROWS];
__device__ float g_pm[NSPLIT * MROWS];
__device__ float g_ps[NSPLIT * MROWS];

__device__ __forceinline__ float fast_exp2(float x) {
    float r; asm("ex2.approx.ftz.f32 %0, %1;" : "=f"(r) : "f"(x)); return r;
}
__device__ __forceinline__ void mma_f16(float* d, const uint32_t* a, const uint32_t* b) {
    asm volatile(
        "mma.sync.aligned.m16n8k16.row.col.f32.f16.f16.f32 "
        "{%0,%1,%2,%3}, {%4,%5,%6,%7}, {%8,%9}, {%0,%1,%2,%3};"
        : "+f"(d[0]), "+f"(d[1]), "+f"(d[2]), "+f"(d[3])
        : "r"(a[0]), "r"(a[1]), "r"(a[2]), "r"(a[3]), "r"(b[0]), "r"(b[1]));
}
__device__ __forceinline__ void ldsm_x4(uint32_t& r0, uint32_t& r1,
                                        uint32_t& r2, uint32_t& r3, uint32_t addr) {
    asm volatile("ldmatrix.sync.aligned.m8n8.x4.shared.b16 {%0,%1,%2,%3}, [%4];"
                 : "=r"(r0), "=r"(r1), "=r"(r2), "=r"(r3) : "r"(addr));
}
__device__ __forceinline__ void cp16(void* smem_dst, const void* gmem_src) {
    uint32_t d = (uint32_t)__cvta_generic_to_shared(smem_dst);
    asm volatile("cp.async.cg.shared.global [%0], [%1], 16;"
                 :: "r"(d), "l"(gmem_src) : "memory");
}

// ---- prep: exact fp32 row norms + fp16(rne) copies (one warp per row) ----
__global__ void prep_kernel(const float* __restrict__ Z, const float* __restrict__ E) {
    int gw = (blockIdx.x * blockDim.x + threadIdx.x) >> 5;
    int lane = threadIdx.x & 31;
    if (gw >= NROWS + MROWS) return;
    const float4* src; uint2* dst;
    if (gw < NROWS) { src = (const float4*)(Z + (size_t)gw * DDIM);
                      dst = (uint2*)(g_zh + (size_t)gw * DDIM); }
    else            { src = (const float4*)(E + (size_t)(gw - NROWS) * DDIM);
                      dst = (uint2*)(g_eh + (size_t)(gw - NROWS) * DDIM); }
    float s = 0.f;
    #pragma unroll
    for (int u = 0; u < DDIM / 4 / 32; u++) {
        float4 v = src[u * 32 + lane];
        s = fmaf(v.x, v.x, s); s = fmaf(v.y, v.y, s);
        s = fmaf(v.z, v.z, s); s = fmaf(v.w, v.w, s);
        __half2 h01 = __floats2half2_rn(v.x, v.y);
        __half2 h23 = __floats2half2_rn(v.z, v.w);
        uint2 w;
        w.x = *reinterpret_cast<uint32_t*>(&h01);
        w.y = *reinterpret_cast<uint32_t*>(&h23);
        dst[u * 32 + lane] = w;
    }
    #pragma unroll
    for (int o = 16; o; o >>= 1) s += __shfl_xor_sync(0xffffffffu, s, o);
    if (lane == 0) { if (gw < NROWS) g_z2[gw] = s; else g_e2[gw - NROWS] = s; }
}

// ---- fused fp16 mma.sync GEMM + online logsumexp ----
__global__ void __launch_bounds__(256, 1) fused_mma_lse(const float* __restrict__ log_sigma) {
    extern __shared__ char smem[];
    char* stg = smem;                                        // NBUF * STAGE_BYTES
    float* az2 = (float*)(smem + NBUF * STAGE_BYTES);        // 2 * ITILE
    float* smm = az2 + 2 * ITILE;                            // 4 * JTILE
    float* sms = smm + 4 * JTILE;                            // 4 * JTILE
    const uint32_t sb32 = (uint32_t)__cvta_generic_to_shared(smem);

    const int tid = threadIdx.x, lane = tid & 31, wid = tid >> 5;
    const int wm = wid & 1, wn = wid >> 1;                   // 2 x 4 warp grid
    const int g = lane >> 2, cql = lane & 3;
    const int jslab = blockIdx.x >> 1, split = blockIdx.x & 1;
    const int j0 = jslab * JTILE, ibase = split * IRANGE;

    // per-lane ldmatrix address components
    const int rA = ((lane >> 3) & 1) * 8 + (lane & 7);  // A: m0 r0-7 c0, m1 r8-15 c0, m2 r0-7 c1, m3 r8-15 c1
    const int cA = (lane >> 4) & 1;
    const int rB = ((lane >> 4) & 1) * 8 + (lane & 7);  // B: m0 r0-7 c0, m1 r0-7 c1, m2 r8-15 c0, m3 r8-15 c1
    const int cB = (lane >> 3) & 1;

    const float ls = __ldg(log_sigma);
    const float alpha = -0.5f * __expf(-2.f * ls);
    const float coefD = LOG2E * (-2.f * alpha);
    const float coefA = LOG2E * alpha;

    float acc[4][8][4];
    #pragma unroll
    for (int mt = 0; mt < 4; mt++)
        #pragma unroll
        for (int nt = 0; nt < 8; nt++)
            #pragma unroll
            for (int q = 0; q < 4; q++) acc[mt][nt][q] = 0.f;
    float mx[8], sv[8];
    #pragma unroll
    for (int r = 0; r < 8; r++) { mx[r] = -INFINITY; sv[r] = 0.f; }

    auto issue_stage = [&](int s) {
        char* base = stg + (s & (NBUF - 1)) * STAGE_BYTES;
        int koff = (s & (KSTAGES - 1)) * KT;          // in halfs
        int i0 = ibase + (s >> 3) * ITILE;
        #pragma unroll
        for (int q = 0; q < 4; q++) {                 // A = E slab: 128 rows x 64 halfs
            int uid = q * 256 + tid, row = uid >> 3, c16 = uid & 7;
            int sc = c16 ^ (row & 7);
            cp16(base + row * 128 + sc * 16,
                 g_eh + (size_t)(j0 + row) * DDIM + koff + c16 * 8);
        }
        #pragma unroll
        for (int q = 0; q < 8; q++) {                 // B = Z chunk: 256 rows x 64 halfs
            int uid = q * 256 + tid, row = uid >> 3, c16 = uid & 7;
            int sc = c16 ^ (row & 7);
            cp16(base + B_BYTES / 2 + row * 128 + sc * 16,   // B_BYTES/2 == A_BYTES
                 g_zh + (size_t)(i0 + row) * DDIM + koff + c16 * 8);
        }
        asm volatile("cp.async.commit_group;" ::: "memory");
    };

    issue_stage(0);
    issue_stage(1);

    #pragma unroll 1
    for (int s = 0; s < TOTSTAGES; s++) {
        asm volatile("cp.async.wait_group 1;" ::: "memory");
        __syncthreads();
        const int t = s >> 3, ks = s & (KSTAGES - 1);
        if (ks == 0)
            az2[(t & 1) * ITILE + tid] = coefA * g_z2[ibase + t * ITILE + tid];
        if (s + 2 < TOTSTAGES) issue_stage(s + 2);

        const uint32_t Ab = sb32 + (s & (NBUF - 1)) * STAGE_BYTES;
        const uint32_t Bb = Ab + A_BYTES;
        #pragma unroll
        for (int kk = 0; kk < KT / 16; kk++) {
            uint32_t a[4][4], b[8][2];
            #pragma unroll
            for (int mt = 0; mt < 4; mt++) {
                int row = wm * 64 + mt * 16 + rA;
                int c16 = kk * 2 + cA;
                ldsm_x4(a[mt][0], a[mt][1], a[mt][2], a[mt][3],
                        Ab + row * 128 + ((c16 ^ (row & 7)) << 4));
            }
            #pragma unroll
            for (int q = 0; q < 4; q++) {
                int row = wn * 64 + q * 16 + rB;
                int c16 = kk * 2 + cB;
                ldsm_x4(b[2 * q][0], b[2 * q][1], b[2 * q + 1][0], b[2 * q + 1][1],
                        Bb + row * 128 + ((c16 ^ (row & 7)) << 4));
            }
            #pragma unroll
            for (int mt = 0; mt < 4; mt++)
                #pragma unroll
                for (int nt = 0; nt < 8; nt++)
                    mma_f16(acc[mt][nt], a[mt], b[nt]);
        }

        if (ks == KSTAGES - 1) {
            // ---- epilogue for chunk t: deferred-rescale online LSE ----
            const float* a2 = az2 + (t & 1) * ITILE;
            float rmx[8];
            #pragma unroll
            for (int r = 0; r < 8; r++) rmx[r] = -INFINITY;
            #pragma unroll
            for (int mt = 0; mt < 4; mt++)
                #pragma unroll
                for (int nt = 0; nt < 8; nt++) {
                    int ib = wn * 64 + nt * 8 + 2 * cql;
                    float s0 = fmaf(coefD, acc[mt][nt][0], a2[ib]);
                    float s1 = fmaf(coefD, acc[mt][nt][1], a2[ib + 1]);
                    float s2 = fmaf(coefD, acc[mt][nt][2], a2[ib]);
                    float s3 = fmaf(coefD, acc[mt][nt][3], a2[ib + 1]);
                    acc[mt][nt][0] = s0; acc[mt][nt][1] = s1;
                    acc[mt][nt][2] = s2; acc[mt][nt][3] = s3;
                    rmx[mt * 2]     = fmaxf(rmx[mt * 2],     fmaxf(s0, s1));
                    rmx[mt * 2 + 1] = fmaxf(rmx[mt * 2 + 1], fmaxf(s2, s3));
                }
            #pragma unroll
            for (int r = 0; r < 8; r++) {
                float nm = fmaxf(mx[r], rmx[r]);
                sv[r] *= fast_exp2(mx[r] - nm);     // first chunk: 0 * ex2(-inf) = 0
                mx[r] = nm;
            }
            #pragma unroll
            for (int mt = 0; mt < 4; mt++) {
                float p0 = 0.f, p1 = 0.f;
                #pragma unroll
                for (int nt = 0; nt < 8; nt++) {
                    p0 += fast_exp2(acc[mt][nt][0] - mx[mt * 2])
                        + fast_exp2(acc[mt][nt][1] - mx[mt * 2]);
                    p1 += fast_exp2(acc[mt][nt][2] - mx[mt * 2 + 1])
                        + fast_exp2(acc[mt][nt][3] - mx[mt * 2 + 1]);
                    acc[mt][nt][0] = 0.f; acc[mt][nt][1] = 0.f;
                    acc[mt][nt][2] = 0.f; acc[mt][nt][3] = 0.f;
                }
                sv[mt * 2] += p0; sv[mt * 2 + 1] += p1;
            }
        }
    }

    // ---- merge 4 lanes (cql) sharing each row ----
    #pragma unroll
    for (int r = 0; r < 8; r++) {
        #pragma unroll
        for (int off = 1; off < 4; off <<= 1) {
            float om = __shfl_xor_sync(0xffffffffu, mx[r], off);
            float os = __shfl_xor_sync(0xffffffffu, sv[r], off);
            float nm = fmaxf(mx[r], om);
            sv[r] = sv[r] * fast_exp2(mx[r] - nm) + os * fast_exp2(om - nm);
            mx[r] = nm;
        }
    }
    __syncthreads();
    if (cql == 0) {
        #pragma unroll
        for (int r = 0; r < 8; r++) {
            int row = wm * 64 + (r >> 1) * 16 + (r & 1) * 8 + g;
            smm[wn * JTILE + row] = mx[r];
            sms[wn * JTILE + row] = sv[r];
        }
    }
    __syncthreads();
    if (tid < JTILE) {
        float gm = -INFINITY;
        #pragma unroll
        for (int w = 0; w < 4; w++) gm = fmaxf(gm, smm[w * JTILE + tid]);
        float gs = 0.f;
        #pragma unroll
        for (int w = 0; w < 4; w++)
            gs += sms[w * JTILE + tid] * fast_exp2(smm[w * JTILE + tid] - gm);
        g_pm[split * MROWS + j0 + tid] = gm;
        g_ps[split * MROWS + j0 + tid] = gs;
    }
}

// ---- finalize: merge splits, add e2 term, mean, constants ----
__global__ void finalize_kernel(const float* __restrict__ log_sigma,
                                float* __restrict__ out) {
    __shared__ double red[256];
    int tid = threadIdx.x;
    float ls = __ldg(log_sigma);
    float alpha = -0.5f * __expf(-2.f * ls);
    double acc = 0.0;
    for (int j = tid; j < MROWS; j += 256) {
        float m0 = g_pm[j],         s0 = g_ps[j];
        float m1 = g_pm[MROWS + j], s1 = g_ps[MROWS + j];
        float gm = fmaxf(m0, m1);
        float s = s0 * exp2f(m0 - gm) + s1 * exp2f(m1 - gm);
        float lse = alpha * g_e2[j] + LN2 * (gm + log2f(s));
        acc += (double)lse;
    }
    red[tid] = acc;
    __syncthreads();
    for (int o = 128; o; o >>= 1) { if (tid < o) red[tid] += red[tid + o]; __syncthreads(); }
    if (tid == 0)
        out[0] = (float)(-red[0] / (double)MROWS)
               + 0.5f * (float)DDIM * (2.f * ls - 1.f) + logf((float)NROWS);
}

extern "C" void kernel_launch(void* const* d_in, const int* in_sizes, int n_in,
                              void* d_out, int out_size) {
    const float* Z  = (const float*)d_in[0];
    const float* E  = (const float*)d_in[1];
    const float* ls = (const float*)d_in[2];
    float* out = (float*)d_out;

    static int smem_set = 0;
    int smem_bytes = NBUF * STAGE_BYTES + (2 * ITILE + 8 * JTILE) * 4;
    if (!smem_set) {
        cudaFuncSetAttribute(fused_mma_lse,
                             cudaFuncAttributeMaxDynamicSharedMemorySize, smem_bytes);
        smem_set = 1;
    }

    prep_kernel<<<(NROWS + MROWS) / 8, 256>>>(Z, E);
    fused_mma_lse<<<(MROWS / JTILE) * NSPLIT, 256, smem_bytes>>>(ls);
    finalize_kernel<<<1, 256>>>(ls, out);
}

// round 5
// speedup vs baseline: 12.6391x; 1.1746x over previous
#include <cuda_runtime.h>
#include <cuda_fp16.h>
#include <math.h>
#include <stdint.h>

// loss = -mean_j [ alpha*e2_j + logsumexp_i( alpha*z2_i - 2*alpha*<z_i,e_j> ) ]
//        + 0.5*D*(2*ls - 1) + log(N)
// fp16 mma.sync.m16n8k16 (fp32 accum) + ldmatrix + XOR-swizzled smem +
// cp.async pipeline. Persistent 148-CTA grid, static tile schedule
// (2048 tiles of 128j x 256i x 512k), per-tile LSE partials, log2 space.

#define NROWS 8192
#define MROWS 8192
#define DDIM  512

#define JTILE 128
#define ITILE 256
#define KT    64                       // k per stage (128B fp16 rows)
#define KSTAGES (DDIM / KT)            // 8
#define SLABS (MROWS / JTILE)          // 64
#define CHUNKS (NROWS / ITILE)         // 32
#define NITEMS (SLABS * CHUNKS)        // 2048
#define GRID 148

#define A_BYTES (JTILE * 128)          // 16384
#define B_BYTES (ITILE * 128)          // 32768
#define STAGE_BYTES (A_BYTES + B_BYTES)
#define NBUF 4

#define LOG2E 1.4426950408889634f
#define LN2   0.6931471805599453f

__device__ __half g_zh[NROWS * DDIM];
__device__ __half g_eh[MROWS * DDIM];
__device__ float g_z2[NROWS];
__device__ float g_e2[MROWS];
__device__ float g_pm[CHUNKS * MROWS];   // per-(chunk,j) max (log2 units)
__device__ float g_ps[CHUNKS * MROWS];   // per-(chunk,j) sum
__device__ double g_acc;

__device__ __forceinline__ float fast_exp2(float x) {
    float r; asm("ex2.approx.ftz.f32 %0, %1;" : "=f"(r) : "f"(x)); return r;
}
__device__ __forceinline__ void mma_f16(float* d, const uint32_t* a, const uint32_t* b) {
    asm volatile(
        "mma.sync.aligned.m16n8k16.row.col.f32.f16.f16.f32 "
        "{%0,%1,%2,%3}, {%4,%5,%6,%7}, {%8,%9}, {%0,%1,%2,%3};"
        : "+f"(d[0]), "+f"(d[1]), "+f"(d[2]), "+f"(d[3])
        : "r"(a[0]), "r"(a[1]), "r"(a[2]), "r"(a[3]), "r"(b[0]), "r"(b[1]));
}
__device__ __forceinline__ void ldsm_x4(uint32_t& r0, uint32_t& r1,
                                        uint32_t& r2, uint32_t& r3, uint32_t addr) {
    asm volatile("ldmatrix.sync.aligned.m8n8.x4.shared.b16 {%0,%1,%2,%3}, [%4];"
                 : "=r"(r0), "=r"(r1), "=r"(r2), "=r"(r3) : "r"(addr));
}
__device__ __forceinline__ void cp16(void* smem_dst, const void* gmem_src) {
    uint32_t d = (uint32_t)__cvta_generic_to_shared(smem_dst);
    asm volatile("cp.async.cg.shared.global [%0], [%1], 16;"
                 :: "r"(d), "l"(gmem_src) : "memory");
}

// ---- prep: exact fp32 row norms + fp16(rne) copies; zero the accumulator ----
__global__ void prep_kernel(const float* __restrict__ Z, const float* __restrict__ E) {
    if (blockIdx.x == 0 && threadIdx.x == 0) g_acc = 0.0;
    int gw = (blockIdx.x * blockDim.x + threadIdx.x) >> 5;
    int lane = threadIdx.x & 31;
    if (gw >= NROWS + MROWS) return;
    const float4* src; uint2* dst;
    if (gw < NROWS) { src = (const float4*)(Z + (size_t)gw * DDIM);
                      dst = (uint2*)(g_zh + (size_t)gw * DDIM); }
    else            { src = (const float4*)(E + (size_t)(gw - NROWS) * DDIM);
                      dst = (uint2*)(g_eh + (size_t)(gw - NROWS) * DDIM); }
    float s = 0.f;
    #pragma unroll
    for (int u = 0; u < DDIM / 4 / 32; u++) {
        float4 v = src[u * 32 + lane];
        s = fmaf(v.x, v.x, s); s = fmaf(v.y, v.y, s);
        s = fmaf(v.z, v.z, s); s = fmaf(v.w, v.w, s);
        __half2 h01 = __floats2half2_rn(v.x, v.y);
        __half2 h23 = __floats2half2_rn(v.z, v.w);
        uint2 w;
        w.x = *reinterpret_cast<uint32_t*>(&h01);
        w.y = *reinterpret_cast<uint32_t*>(&h23);
        dst[u * 32 + lane] = w;
    }
    #pragma unroll
    for (int o = 16; o; o >>= 1) s += __shfl_xor_sync(0xffffffffu, s, o);
    if (lane == 0) { if (gw < NROWS) g_z2[gw] = s; else g_e2[gw - NROWS] = s; }
}

// ---- persistent fused fp16 mma GEMM + per-tile LSE partials ----
__global__ void __launch_bounds__(256, 1) fused_mma_lse(const float* __restrict__ log_sigma) {
    extern __shared__ char smem[];
    char* stg = smem;                                        // NBUF * STAGE_BYTES
    float* az2 = (float*)(smem + NBUF * STAGE_BYTES);        // 2 * ITILE
    float* smm = az2 + 2 * ITILE;                            // 4 * JTILE
    float* sms = smm + 4 * JTILE;                            // 4 * JTILE
    const uint32_t sb32 = (uint32_t)__cvta_generic_to_shared(smem);

    const int tid = threadIdx.x, lane = tid & 31, wid = tid >> 5;
    const int wm = wid & 1, wn = wid >> 1;                   // 2 x 4 warp grid
    const int g = lane >> 2, cql = lane & 3;
    const int cta = blockIdx.x;

    const int nitems = (NITEMS - cta + GRID - 1) / GRID;     // 13 or 14
    const int tot = nitems * KSTAGES;

    // ldmatrix per-lane addressing
    const int rA = ((lane >> 3) & 1) * 8 + (lane & 7);
    const int cA = (lane >> 4) & 1;
    const int rB = ((lane >> 4) & 1) * 8 + (lane & 7);
    const int cB = (lane >> 3) & 1;

    const float ls = __ldg(log_sigma);
    const float alpha = -0.5f * __expf(-2.f * ls);
    const float coefD = LOG2E * (-2.f * alpha);
    const float coefA = LOG2E * alpha;

    float acc[4][8][4];
    #pragma unroll
    for (int mt = 0; mt < 4; mt++)
        #pragma unroll
        for (int nt = 0; nt < 8; nt++)
            #pragma unroll
            for (int q = 0; q < 4; q++) acc[mt][nt][q] = 0.f;

    auto issue_stage = [&](int ss) {
        int q = ss >> 3, ks = ss & (KSTAGES - 1);
        int item = cta + q * GRID;
        int j0 = (item >> 5) * JTILE;
        int i0 = (item & (CHUNKS - 1)) * ITILE;
        char* base = stg + (ss & (NBUF - 1)) * STAGE_BYTES;
        int koff = ks * KT;
        #pragma unroll
        for (int u = 0; u < 4; u++) {                 // A = E slab: 128 x 64h
            int uid = u * 256 + tid, row = uid >> 3, c16 = uid & 7;
            int sc = c16 ^ (row & 7);
            cp16(base + row * 128 + sc * 16,
                 g_eh + (size_t)(j0 + row) * DDIM + koff + c16 * 8);
        }
        #pragma unroll
        for (int u = 0; u < 8; u++) {                 // B = Z chunk: 256 x 64h
            int uid = u * 256 + tid, row = uid >> 3, c16 = uid & 7;
            int sc = c16 ^ (row & 7);
            cp16(base + A_BYTES + row * 128 + sc * 16,
                 g_zh + (size_t)(i0 + row) * DDIM + koff + c16 * 8);
        }
        asm volatile("cp.async.commit_group;" ::: "memory");
    };

    issue_stage(0);
    issue_stage(1);

    #pragma unroll 1
    for (int ss = 0; ss < tot; ss++) {
        asm volatile("cp.async.wait_group 1;" ::: "memory");
        __syncthreads();
        const int q = ss >> 3, ks = ss & (KSTAGES - 1);
        const int item = cta + q * GRID;
        const int chunk = item & (CHUNKS - 1);
        const int j0 = (item >> 5) * JTILE;
        if (ks == 0)
            az2[(q & 1) * ITILE + tid] = coefA * g_z2[chunk * ITILE + tid];
        if (ss + 2 < tot) issue_stage(ss + 2);

        const uint32_t Ab = sb32 + (ss & (NBUF - 1)) * STAGE_BYTES;
        const uint32_t Bb = Ab + A_BYTES;
        #pragma unroll
        for (int kk = 0; kk < KT / 16; kk++) {
            uint32_t a[4][4], b[8][2];
            #pragma unroll
            for (int mt = 0; mt < 4; mt++) {
                int row = wm * 64 + mt * 16 + rA;
                int c16 = kk * 2 + cA;
                ldsm_x4(a[mt][0], a[mt][1], a[mt][2], a[mt][3],
                        Ab + row * 128 + ((c16 ^ (row & 7)) << 4));
            }
            #pragma unroll
            for (int u = 0; u < 4; u++) {
                int row = wn * 64 + u * 16 + rB;
                int c16 = kk * 2 + cB;
                ldsm_x4(b[2 * u][0], b[2 * u][1], b[2 * u + 1][0], b[2 * u + 1][1],
                        Bb + row * 128 + ((c16 ^ (row & 7)) << 4));
            }
            #pragma unroll
            for (int mt = 0; mt < 4; mt++)
                #pragma unroll
                for (int nt = 0; nt < 8; nt++)
                    mma_f16(acc[mt][nt], a[mt], b[nt]);
        }

        if (ks == KSTAGES - 1) {
            // ---- per-tile epilogue: max + sum over this 128x256 tile ----
            const float* a2 = az2 + (q & 1) * ITILE;
            float mx[8], sv[8];
            #pragma unroll
            for (int r = 0; r < 8; r++) mx[r] = -INFINITY;
            #pragma unroll
            for (int mt = 0; mt < 4; mt++)
                #pragma unroll
                for (int nt = 0; nt < 8; nt++) {
                    int ib = wn * 64 + nt * 8 + 2 * cql;
                    float s0 = fmaf(coefD, acc[mt][nt][0], a2[ib]);
                    float s1 = fmaf(coefD, acc[mt][nt][1], a2[ib + 1]);
                    float s2 = fmaf(coefD, acc[mt][nt][2], a2[ib]);
                    float s3 = fmaf(coefD, acc[mt][nt][3], a2[ib + 1]);
                    acc[mt][nt][0] = s0; acc[mt][nt][1] = s1;
                    acc[mt][nt][2] = s2; acc[mt][nt][3] = s3;
                    mx[mt * 2]     = fmaxf(mx[mt * 2],     fmaxf(s0, s1));
                    mx[mt * 2 + 1] = fmaxf(mx[mt * 2 + 1], fmaxf(s2, s3));
                }
            #pragma unroll
            for (int mt = 0; mt < 4; mt++) {
                float p0 = 0.f, p1 = 0.f;
                #pragma unroll
                for (int nt = 0; nt < 8; nt++) {
                    p0 += fast_exp2(acc[mt][nt][0] - mx[mt * 2])
                        + fast_exp2(acc[mt][nt][1] - mx[mt * 2]);
                    p1 += fast_exp2(acc[mt][nt][2] - mx[mt * 2 + 1])
                        + fast_exp2(acc[mt][nt][3] - mx[mt * 2 + 1]);
                    acc[mt][nt][0] = 0.f; acc[mt][nt][1] = 0.f;
                    acc[mt][nt][2] = 0.f; acc[mt][nt][3] = 0.f;
                }
                sv[mt * 2] = p0; sv[mt * 2 + 1] = p1;
            }
            // merge 4 lanes (cql) sharing each row
            #pragma unroll
            for (int r = 0; r < 8; r++) {
                #pragma unroll
                for (int off = 1; off < 4; off <<= 1) {
                    float om = __shfl_xor_sync(0xffffffffu, mx[r], off);
                    float os = __shfl_xor_sync(0xffffffffu, sv[r], off);
                    float nm = fmaxf(mx[r], om);
                    sv[r] = sv[r] * fast_exp2(mx[r] - nm) + os * fast_exp2(om - nm);
                    mx[r] = nm;
                }
            }
            __syncthreads();
            if (cql == 0) {
                #pragma unroll
                for (int r = 0; r < 8; r++) {
                    int row = wm * 64 + (r >> 1) * 16 + (r & 1) * 8 + g;
                    smm[wn * JTILE + row] = mx[r];
                    sms[wn * JTILE + row] = sv[r];
                }
            }
            __syncthreads();
            if (tid < JTILE) {
                float gm = -INFINITY;
                #pragma unroll
                for (int w = 0; w < 4; w++) gm = fmaxf(gm, smm[w * JTILE + tid]);
                float gs = 0.f;
                #pragma unroll
                for (int w = 0; w < 4; w++)
                    gs += sms[w * JTILE + tid] * fast_exp2(smm[w * JTILE + tid] - gm);
                g_pm[chunk * MROWS + j0 + tid] = gm;
                g_ps[chunk * MROWS + j0 + tid] = gs;
            }
        }
    }
}

// ---- finalize: merge 32 chunk-partials per column, block-partial atomics ----
__global__ void finalize1_kernel(const float* __restrict__ log_sigma) {
    __shared__ double red[256];
    int tid = threadIdx.x;
    int j = blockIdx.x * 256 + tid;     // 32 blocks x 256 = 8192 columns
    float ls = __ldg(log_sigma);
    float alpha = -0.5f * __expf(-2.f * ls);
    float gm = -INFINITY;
    #pragma unroll
    for (int c = 0; c < CHUNKS; c++) gm = fmaxf(gm, g_pm[c * MROWS + j]);
    float s = 0.f;
    #pragma unroll
    for (int c = 0; c < CHUNKS; c++)
        s += g_ps[c * MROWS + j] * exp2f(g_pm[c * MROWS + j] - gm);
    float lse = alpha * g_e2[j] + LN2 * (gm + log2f(s));
    red[tid] = (double)lse;
    __syncthreads();
    for (int o = 128; o; o >>= 1) { if (tid < o) red[tid] += red[tid + o]; __syncthreads(); }
    if (tid == 0) atomicAdd(&g_acc, red[0]);
}

__global__ void finalize2_kernel(const float* __restrict__ log_sigma,
                                 float* __restrict__ out) {
    float ls = *log_sigma;
    out[0] = (float)(-g_acc / (double)MROWS)
           + 0.5f * (float)DDIM * (2.f * ls - 1.f) + logf((float)NROWS);
}

extern "C" void kernel_launch(void* const* d_in, const int* in_sizes, int n_in,
                              void* d_out, int out_size) {
    const float* Z  = (const float*)d_in[0];
    const float* E  = (const float*)d_in[1];
    const float* ls = (const float*)d_in[2];
    float* out = (float*)d_out;

    static int smem_set = 0;
    int smem_bytes = NBUF * STAGE_BYTES + (2 * ITILE + 8 * JTILE) * 4;
    if (!smem_set) {
        cudaFuncSetAttribute(fused_mma_lse,
                             cudaFuncAttributeMaxDynamicSharedMemorySize, smem_bytes);
        smem_set = 1;
    }

    prep_kernel<<<(NROWS + MROWS) / 8, 256>>>(Z, E);
    fused_mma_lse<<<GRID, 256, smem_bytes>>>(ls);
    finalize1_kernel<<<MROWS / 256, 256>>>(ls);
    finalize2_kernel<<<1, 1>>>(ls, out);
}